// round 6
// baseline (speedup 1.0000x reference)
#include <cuda_runtime.h>

// ---------------------------------------------------------------------------
// GCN 2-layer, round 6: ONE persistent kernel, software grid barriers.
// Phases: zero/detect | gemm1+edge-decode pool | block scan | sum scan |
//         CSR fill | gather1+gemm2 | gather2+softmax
// ---------------------------------------------------------------------------

#define MAXN 131072
#define MAXE 4194304
#define IN_CH 256
#define HID 64
#define OUT_CH 16
#define NT 256
#define KT 16
#define PREP_CHUNK 8192

__device__ float g_h1[(size_t)MAXN * HID];
__device__ float g_h2[(size_t)MAXN * OUT_CH];
__device__ float g_dinv[MAXN];
__device__ int   g_incnt[MAXN];
__device__ int   g_rowstart[MAXN];   // block-local exclusive prefix
__device__ int   g_fill[MAXN];       // slot counters
__device__ int   g_blocksum[1024];
__device__ int2  g_edge[MAXE];
__device__ int2  g_csr[MAXE];        // (src, norm-bits) grouped by dst
__device__ int   g_is64;
__device__ int   g_wq;                       // phase-B work counter
__device__ unsigned g_barcnt;                // grid barrier arrive count
__device__ volatile unsigned g_bargen;       // grid barrier generation

__device__ __forceinline__ void gridbar() {
    __syncthreads();
    if (threadIdx.x == 0) {
        __threadfence();
        unsigned gen = g_bargen;
        unsigned t = atomicAdd(&g_barcnt, 1u);
        if (t == gridDim.x - 1) {
            g_barcnt = 0;
            __threadfence();
            g_bargen = gen + 1;
        } else {
            while (g_bargen == gen) __nanosleep(40);
        }
        __threadfence();
    }
    __syncthreads();
}

__device__ __forceinline__ int ldidx(const void* ei, long long i, int is64) {
    if (is64) return (int)__ldg(((const long long*)ei) + i);
    return __ldg(((const int*)ei) + i);
}

__device__ __forceinline__ int rowstart(int i) {
    return g_rowstart[i] + g_blocksum[i >> 8];
}

__global__ __launch_bounds__(NT, 2) void k_all(
    const float* __restrict__ x, const void* __restrict__ ei,
    const float* __restrict__ W1, const float* __restrict__ b1,
    const float* __restrict__ W2, const float* __restrict__ b2,
    float* __restrict__ out, int N, long long E, int nwords)
{
    __shared__ float Xs[KT][132];
    __shared__ float Ws[KT][64];
    __shared__ float ts[16][68];
    __shared__ float W2t[16][68];
    __shared__ float b1s[64];
    __shared__ int   sA[512], sB[512];
    __shared__ int   wsum[8];
    __shared__ int   s_item;

    int tid = threadIdx.x;
    int bid = blockIdx.x;
    int nb  = gridDim.x;
    int gtid = bid * NT + tid;
    int gstride = nb * NT;
    int lane = tid & 31, wid = tid >> 5;

    // ---- Phase A: zero counters, detect dtype, reset work counter ---------
    for (int i = gtid; i < N; i += gstride) { g_incnt[i] = 0; g_fill[i] = 0; }
    // stage W2^T and b1 for phase F (input-only, safe here)
    for (int i = tid; i < 64 * 16; i += NT) W2t[i & 15][i >> 4] = W2[i];
    if (tid < 64) b1s[tid] = b1[tid];
    if (bid == 0) {
        const long long* p = (const long long*)ei;
        int ok = 1;
        #pragma unroll
        for (int j = 0; j < 8; j++) {
            int w = tid * 8 + j;
            if (w < nwords) {
                long long v = __ldg(p + w);
                if (v < 0 || v >= (long long)N) ok = 0;
            }
        }
        int all = __syncthreads_and(ok);
        if (tid == 0) { g_is64 = all; g_wq = 0; }
    }
    gridbar();

    // ---- Phase B: dynamic pool — gemm1 tiles + edge decode chunks ---------
    int nbG = (N + 127) / 128;
    int nchunks = (int)((E + PREP_CHUNK - 1) / PREP_CHUNK);
    int is64 = g_is64;
    for (;;) {
        __syncthreads();
        if (tid == 0) s_item = atomicAdd(&g_wq, 1);
        __syncthreads();
        int item = s_item;
        if (item >= nbG + nchunks) break;
        if (item < nbG) {
            // ---- gemm1 tile: 128 nodes x 64 feats ----
            int node0 = item * 128;
            int na = (lane) * 4;          // tid&31 * 4
            int fb = (wid) * 8;           // tid>>5 * 8
            float acc[4][8];
            #pragma unroll
            for (int i = 0; i < 4; i++)
                #pragma unroll
                for (int j = 0; j < 8; j++) acc[i][j] = 0.f;
            for (int kk = 0; kk < IN_CH; kk += KT) {
                {
                    const float4* wg = (const float4*)(W1 + (size_t)kk * 64);
                    ((float4*)Ws)[tid] = wg[tid];
                }
                #pragma unroll
                for (int half = 0; half < 2; half++) {
                    int i = tid + half * NT;
                    int n = i >> 2;
                    int kq = i & 3;
                    int gnode = node0 + n;
                    float4 v = (gnode < N)
                        ? *(const float4*)(x + (size_t)gnode * IN_CH + kk + kq * 4)
                        : make_float4(0.f, 0.f, 0.f, 0.f);
                    Xs[kq * 4 + 0][n] = v.x;
                    Xs[kq * 4 + 1][n] = v.y;
                    Xs[kq * 4 + 2][n] = v.z;
                    Xs[kq * 4 + 3][n] = v.w;
                }
                __syncthreads();
                #pragma unroll
                for (int k = 0; k < KT; k++) {
                    float4 a   = *(const float4*)&Xs[k][na];
                    float4 b0  = *(const float4*)&Ws[k][fb];
                    float4 b1v = *(const float4*)&Ws[k][fb + 4];
                    float av[4] = {a.x, a.y, a.z, a.w};
                    float bv[8] = {b0.x, b0.y, b0.z, b0.w, b1v.x, b1v.y, b1v.z, b1v.w};
                    #pragma unroll
                    for (int i = 0; i < 4; i++)
                        #pragma unroll
                        for (int j = 0; j < 8; j++)
                            acc[i][j] += av[i] * bv[j];
                }
                __syncthreads();
            }
            #pragma unroll
            for (int i = 0; i < 4; i++) {
                int node = node0 + na + i;
                if (node < N) {
                    *(float4*)(g_h1 + (size_t)node * HID + fb) =
                        make_float4(acc[i][0], acc[i][1], acc[i][2], acc[i][3]);
                    *(float4*)(g_h1 + (size_t)node * HID + fb + 4) =
                        make_float4(acc[i][4], acc[i][5], acc[i][6], acc[i][7]);
                }
            }
        } else {
            // ---- edge decode chunk ----
            long long s0 = (long long)(item - nbG) * PREP_CHUNK;
            long long s1 = s0 + PREP_CHUNK; if (s1 > E) s1 = E;
            for (long long e = s0 + tid; e < s1; e += NT) {
                int s = ldidx(ei, e, is64);
                int d = ldidx(ei, E + e, is64);
                g_edge[e] = make_int2(s, d);
                atomicAdd(&g_incnt[d], 1);
            }
        }
    }
    gridbar();

    // ---- Phase C: block-local scans of g_incnt + dinv ---------------------
    int nbS = (N + 255) / 256;
    for (int cb = bid; cb < nbS; cb += nb) {
        int i = cb * 256 + tid;
        int v = (i < N) ? g_incnt[i] : 0;
        if (i < N) g_dinv[i] = rsqrtf((float)(v + 1));
        int xv = v;
        #pragma unroll
        for (int o = 1; o < 32; o <<= 1) {
            int y = __shfl_up_sync(0xffffffffu, xv, o);
            if (lane >= o) xv += y;
        }
        if (lane == 31) wsum[wid] = xv;
        __syncthreads();
        if (wid == 0) {
            int s = (lane < 8) ? wsum[lane] : 0;
            #pragma unroll
            for (int o = 1; o < 8; o <<= 1) {
                int y = __shfl_up_sync(0xffffffffu, s, o);
                if (lane >= o) s += y;
            }
            if (lane < 8) wsum[lane] = s;
        }
        __syncthreads();
        int excl = xv - v + (wid > 0 ? wsum[wid - 1] : 0);
        if (i < N) g_rowstart[i] = excl;
        if (tid == 255) g_blocksum[cb] = excl + v;
        __syncthreads();
    }
    gridbar();

    // ---- Phase D: scan blocksums (block 0 only, <=512 values) -------------
    if (bid == 0) {
        int v0 = (tid < nbS) ? g_blocksum[tid] : 0;
        int v1 = (tid + 256 < nbS) ? g_blocksum[tid + 256] : 0;
        sA[tid] = v0; sA[tid + 256] = v1;
        __syncthreads();
        int* src = sA; int* dst = sB;
        for (int o = 1; o < 512; o <<= 1) {
            dst[tid]       = src[tid]       + ((tid >= o)       ? src[tid - o]       : 0);
            dst[tid + 256] = src[tid + 256] + ((tid + 256 >= o) ? src[tid + 256 - o] : 0);
            __syncthreads();
            int* t = src; src = dst; dst = t;
        }
        if (tid < nbS) g_blocksum[tid] = src[tid] - v0;
        if (tid + 256 < nbS) g_blocksum[tid + 256] = src[tid + 256] - v1;
    }
    gridbar();

    // ---- Phase E: fill CSR ------------------------------------------------
    for (long long e0 = (long long)gtid * 2; e0 < E; e0 += (long long)gstride * 2) {
        int4 two = *(const int4*)&g_edge[e0];
        {
            int s = two.x, d = two.y;
            float nrm = g_dinv[s] * g_dinv[d];
            int pos = rowstart(d) + atomicAdd(&g_fill[d], 1);
            g_csr[pos] = make_int2(s, __float_as_int(nrm));
        }
        if (e0 + 1 < E) {
            int s = two.z, d = two.w;
            float nrm = g_dinv[s] * g_dinv[d];
            int pos = rowstart(d) + atomicAdd(&g_fill[d], 1);
            g_csr[pos] = make_int2(s, __float_as_int(nrm));
        }
    }
    gridbar();

    // ---- Phase F: gather1 + gemm2 (16 nodes/tile, 16 thr/node) ------------
    int nTiles = (N + 15) / 16;
    for (int tile = bid; tile < nTiles; tile += nb) {
        int li = tid >> 4, c = tid & 15;
        int node = tile * 16 + li;
        bool valid = node < N;
        if (!valid) node = N - 1;
        float di = g_dinv[node];
        float sc = di * di;
        float4 acc = ((const float4*)(g_h1 + (size_t)node * HID))[c];
        acc.x *= sc; acc.y *= sc; acc.z *= sc; acc.w *= sc;
        int e = rowstart(node);
        int end = e + g_incnt[node];
        for (; e + 1 < end; e += 2) {
            int2 c0 = g_csr[e], c1 = g_csr[e + 1];
            float n0 = __int_as_float(c0.y), n1 = __int_as_float(c1.y);
            float4 v0 = ((const float4*)(g_h1 + (size_t)c0.x * HID))[c];
            float4 v1 = ((const float4*)(g_h1 + (size_t)c1.x * HID))[c];
            acc.x += v0.x * n0; acc.y += v0.y * n0;
            acc.z += v0.z * n0; acc.w += v0.w * n0;
            acc.x += v1.x * n1; acc.y += v1.y * n1;
            acc.z += v1.z * n1; acc.w += v1.w * n1;
        }
        if (e < end) {
            int2 c0 = g_csr[e];
            float n0 = __int_as_float(c0.y);
            float4 v0 = ((const float4*)(g_h1 + (size_t)c0.x * HID))[c];
            acc.x += v0.x * n0; acc.y += v0.y * n0;
            acc.z += v0.z * n0; acc.w += v0.w * n0;
        }
        float4 b = *(const float4*)&b1s[c * 4];
        acc.x = fmaxf(acc.x + b.x, 0.f);
        acc.y = fmaxf(acc.y + b.y, 0.f);
        acc.z = fmaxf(acc.z + b.z, 0.f);
        acc.w = fmaxf(acc.w + b.w, 0.f);
        *(float4*)&ts[li][c * 4] = acc;
        __syncthreads();
        float h2 = 0.f;
        #pragma unroll
        for (int k = 0; k < 64; k += 4) {
            float4 t = *(const float4*)&ts[li][k];
            float4 w = *(const float4*)&W2t[c][k];
            h2 += t.x * w.x + t.y * w.y + t.z * w.z + t.w * w.w;
        }
        if (valid) g_h2[(size_t)node * OUT_CH + c] = h2;
        __syncthreads();
    }
    gridbar();

    // ---- Phase G: gather2 + bias + log_softmax ----------------------------
    // 64-node chunks; N%64 in {0,32} keeps warp-granular exits (shfl-safe).
    for (int base = bid * 64; base < N; base += nb * 64) {
        int li = tid >> 2, c = tid & 3;
        int node = base + li;
        if (node >= N) continue;
        float di = g_dinv[node];
        float sc = di * di;
        float4 acc = ((const float4*)(g_h2 + (size_t)node * OUT_CH))[c];
        acc.x *= sc; acc.y *= sc; acc.z *= sc; acc.w *= sc;
        int e = rowstart(node);
        int end = e + g_incnt[node];
        for (; e + 1 < end; e += 2) {
            int2 c0 = g_csr[e], c1 = g_csr[e + 1];
            float n0 = __int_as_float(c0.y), n1 = __int_as_float(c1.y);
            float4 v0 = ((const float4*)(g_h2 + (size_t)c0.x * OUT_CH))[c];
            float4 v1 = ((const float4*)(g_h2 + (size_t)c1.x * OUT_CH))[c];
            acc.x += v0.x * n0; acc.y += v0.y * n0;
            acc.z += v0.z * n0; acc.w += v0.w * n0;
            acc.x += v1.x * n1; acc.y += v1.y * n1;
            acc.z += v1.z * n1; acc.w += v1.w * n1;
        }
        if (e < end) {
            int2 c0 = g_csr[e];
            float n0 = __int_as_float(c0.y);
            float4 v0 = ((const float4*)(g_h2 + (size_t)c0.x * OUT_CH))[c];
            acc.x += v0.x * n0; acc.y += v0.y * n0;
            acc.z += v0.z * n0; acc.w += v0.w * n0;
        }
        float4 b = ((const float4*)b2)[c];
        acc.x += b.x; acc.y += b.y; acc.z += b.z; acc.w += b.w;
        float m = fmaxf(fmaxf(acc.x, acc.y), fmaxf(acc.z, acc.w));
        m = fmaxf(m, __shfl_xor_sync(0xffffffffu, m, 1));
        m = fmaxf(m, __shfl_xor_sync(0xffffffffu, m, 2));
        float se = expf(acc.x - m) + expf(acc.y - m) + expf(acc.z - m) + expf(acc.w - m);
        se += __shfl_xor_sync(0xffffffffu, se, 1);
        se += __shfl_xor_sync(0xffffffffu, se, 2);
        float l = m + logf(se);
        acc.x -= l; acc.y -= l; acc.z -= l; acc.w -= l;
        ((float4*)(out + (size_t)node * OUT_CH))[c] = acc;
    }
}

// ---------------------------------------------------------------------------
extern "C" void kernel_launch(void* const* d_in, const int* in_sizes, int n_in,
                              void* d_out, int out_size) {
    const float* x  = (const float*)d_in[0];
    const void*  ei = d_in[1];
    const float* W1 = (const float*)d_in[2];
    const float* b1 = (const float*)d_in[3];
    const float* W2 = (const float*)d_in[4];
    const float* b2 = (const float*)d_in[5];
    float* out = (float*)d_out;

    int N = in_sizes[0] / IN_CH;
    long long E = in_sizes[1] / 2;
    int nwords = (int)((E < 2048) ? E : 2048);

    int sms = 148;
    cudaDeviceGetAttribute(&sms, cudaDevAttrMultiProcessorCount, 0);
    int nblocks = sms * 2;   // __launch_bounds__(256,2) guarantees residency

    k_all<<<nblocks, NT>>>(x, ei, W1, b1, W2, b2, out, N, E, nwords);
}

// round 7
// speedup vs baseline: 1.5046x; 1.5046x over previous
#include <cuda_runtime.h>
#include <cuda_fp16.h>

// ---------------------------------------------------------------------------
// GCN 2-layer, round 7: 5 launches. fp16 h1 storage (halves gather-1 traffic),
// pool kernel overlaps gemm1 with edge decode, single-pass scan (last-block),
// counter zeroing folded into gather2 tail (static zero-init covers call #1).
// ---------------------------------------------------------------------------

#define MAXN 131072
#define MAXE 4194304
#define IN_CH 256
#define HID 64
#define OUT_CH 16
#define KT 16
#define PREP_CHUNK 8192

__device__ __half2 g_h1h[(size_t)MAXN * 32];   // h1 in fp16, 32 half2 per row
__device__ float g_h2[(size_t)MAXN * OUT_CH];
__device__ float g_dinv[MAXN];
__device__ int   g_incnt[MAXN];      // zero at entry (static init / gather2 tail)
__device__ int   g_rowstart[MAXN];   // block-local exclusive prefix
__device__ int   g_fill[MAXN];       // zero at entry (same mechanism)
__device__ int   g_blocksum[1024];
__device__ int   g_scan_count;       // zero at entry; last scan block resets
__device__ int2  g_edge[MAXE];
__device__ int2  g_csr[MAXE];        // (src, norm-bits) grouped by dst

__device__ __forceinline__ int rowstart(int i) {
    return g_rowstart[i] + g_blocksum[i >> 8];
}

// load 4 consecutive fp16 features (chunk c) of node's h1 row as float4
__device__ __forceinline__ float4 h1load(int node, int c) {
    uint2 u = *(const uint2*)(g_h1h + (size_t)node * 32 + c * 2);
    float2 f0 = __half22float2(*(__half2*)&u.x);
    float2 f1 = __half22float2(*(__half2*)&u.y);
    return make_float4(f0.x, f0.y, f1.x, f1.y);
}

// ---- pool: gemm1 tiles interleaved with edge-decode chunks ----------------
// Ticket mapping: every 4th ticket (q%4==3) is a prep chunk while chunks
// remain; grid is sized so all chunks are covered.
__global__ __launch_bounds__(256) void k_pool(const float* __restrict__ x,
                                              const void* __restrict__ ei,
                                              const float* __restrict__ W1,
                                              int N, long long E,
                                              int nbG, int nchunks, int nwords) {
    __shared__ float Xs[KT][132];
    __shared__ float Ws[KT][64];
    int tid = threadIdx.x;
    int q = blockIdx.x;

    bool isprep = ((q & 3) == 3) && ((q >> 2) < nchunks);
    if (isprep) {
        // local dtype probe (cheap, L2-cached): int32 data read as int64 is
        // out of [0,N) with prob ~1 per word.
        const long long* p = (const long long*)ei;
        int ok = 1;
        #pragma unroll
        for (int j = 0; j < 2; j++) {
            int w = tid + j * 256;
            if (w < nwords) {
                long long v = __ldg(p + w);
                if (v < 0 || v >= (long long)N) ok = 0;
            }
        }
        int is64 = __syncthreads_and(ok);
        long long s0 = (long long)(q >> 2) * PREP_CHUNK;
        long long s1 = s0 + PREP_CHUNK; if (s1 > E) s1 = E;
        if (is64) {
            const long long* pp = (const long long*)ei;
            for (long long e = s0 + tid; e < s1; e += 256) {
                int s = (int)__ldg(pp + e);
                int d = (int)__ldg(pp + E + e);
                g_edge[e] = make_int2(s, d);
                atomicAdd(&g_incnt[d], 1);
            }
        } else {
            const int* pp = (const int*)ei;
            for (long long e = s0 + tid; e < s1; e += 256) {
                int s = __ldg(pp + e);
                int d = __ldg(pp + E + e);
                g_edge[e] = make_int2(s, d);
                atomicAdd(&g_incnt[d], 1);
            }
        }
        return;
    }

    int g = q - min(q >> 2, nchunks);
    if (g >= nbG) return;

    // ---- gemm1 tile: 128 nodes x 64 feats, 4x8 micro-tile ----
    int node0 = g * 128;
    int lane = tid & 31, wid = tid >> 5;
    int na = lane * 4;
    int fb = wid * 8;
    float acc[4][8];
    #pragma unroll
    for (int i = 0; i < 4; i++)
        #pragma unroll
        for (int j = 0; j < 8; j++) acc[i][j] = 0.f;

    for (int kk = 0; kk < IN_CH; kk += KT) {
        {
            const float4* wg = (const float4*)(W1 + (size_t)kk * 64);
            ((float4*)Ws)[tid] = wg[tid];
        }
        #pragma unroll
        for (int half = 0; half < 2; half++) {
            int i = tid + half * 256;
            int n = i >> 2;
            int kq = i & 3;
            int gnode = node0 + n;
            float4 v = (gnode < N)
                ? *(const float4*)(x + (size_t)gnode * IN_CH + kk + kq * 4)
                : make_float4(0.f, 0.f, 0.f, 0.f);
            Xs[kq * 4 + 0][n] = v.x;
            Xs[kq * 4 + 1][n] = v.y;
            Xs[kq * 4 + 2][n] = v.z;
            Xs[kq * 4 + 3][n] = v.w;
        }
        __syncthreads();
        #pragma unroll
        for (int k = 0; k < KT; k++) {
            float4 a   = *(const float4*)&Xs[k][na];
            float4 b0  = *(const float4*)&Ws[k][fb];
            float4 b1v = *(const float4*)&Ws[k][fb + 4];
            float av[4] = {a.x, a.y, a.z, a.w};
            float bv[8] = {b0.x, b0.y, b0.z, b0.w, b1v.x, b1v.y, b1v.z, b1v.w};
            #pragma unroll
            for (int i = 0; i < 4; i++)
                #pragma unroll
                for (int j = 0; j < 8; j++)
                    acc[i][j] += av[i] * bv[j];
        }
        __syncthreads();
    }
    #pragma unroll
    for (int i = 0; i < 4; i++) {
        int node = node0 + na + i;
        if (node < N) {
            union { __half2 h[4]; uint4 u; } pk;
            pk.h[0] = __floats2half2_rn(acc[i][0], acc[i][1]);
            pk.h[1] = __floats2half2_rn(acc[i][2], acc[i][3]);
            pk.h[2] = __floats2half2_rn(acc[i][4], acc[i][5]);
            pk.h[3] = __floats2half2_rn(acc[i][6], acc[i][7]);
            *(uint4*)(g_h1h + (size_t)node * 32 + (fb >> 1)) = pk.u;
        }
    }
}

// ---- single-pass scan: block scans + last-block scans the block sums ------
__global__ __launch_bounds__(256) void k_scan(int N, int nbS) {
    __shared__ int wsum[8];
    __shared__ int sA[512], sB[512];
    __shared__ int s_last;
    int tid = threadIdx.x, lane = tid & 31, wid = tid >> 5;
    int cb = blockIdx.x;
    int i = cb * 256 + tid;
    int v = (i < N) ? g_incnt[i] : 0;
    if (i < N) g_dinv[i] = rsqrtf((float)(v + 1));  // +1 self-loop
    int xv = v;
    #pragma unroll
    for (int o = 1; o < 32; o <<= 1) {
        int y = __shfl_up_sync(0xffffffffu, xv, o);
        if (lane >= o) xv += y;
    }
    if (lane == 31) wsum[wid] = xv;
    __syncthreads();
    if (wid == 0) {
        int s = (lane < 8) ? wsum[lane] : 0;
        #pragma unroll
        for (int o = 1; o < 8; o <<= 1) {
            int y = __shfl_up_sync(0xffffffffu, s, o);
            if (lane >= o) s += y;
        }
        if (lane < 8) wsum[lane] = s;
    }
    __syncthreads();
    int excl = xv - v + (wid > 0 ? wsum[wid - 1] : 0);
    if (i < N) g_rowstart[i] = excl;
    if (tid == 255) {
        g_blocksum[cb] = excl + v;
        __threadfence();
        s_last = (atomicAdd(&g_scan_count, 1) == nbS - 1) ? 1 : 0;
    }
    __syncthreads();
    if (s_last) {
        __threadfence();
        int v0 = (tid < nbS) ? g_blocksum[tid] : 0;
        int v1 = (tid + 256 < nbS) ? g_blocksum[tid + 256] : 0;
        sA[tid] = v0; sA[tid + 256] = v1;
        __syncthreads();
        int* src = sA; int* dst = sB;
        for (int o = 1; o < 512; o <<= 1) {
            dst[tid]       = src[tid]       + ((tid >= o)       ? src[tid - o]       : 0);
            dst[tid + 256] = src[tid + 256] + ((tid + 256 >= o) ? src[tid + 256 - o] : 0);
            __syncthreads();
            int* t = src; src = dst; dst = t;
        }
        if (tid < nbS) g_blocksum[tid] = src[tid] - v0;
        if (tid + 256 < nbS) g_blocksum[tid + 256] = src[tid + 256] - v1;
        if (tid == 0) g_scan_count = 0;   // reset for next call
    }
}

// ---- fill CSR: (src, norm) grouped by dst ---------------------------------
__global__ __launch_bounds__(256) void k_fill(long long E) {
    long long e0 = ((long long)blockIdx.x * 256 + threadIdx.x) * 2;
    if (e0 >= E) return;
    int4 two = *(const int4*)&g_edge[e0];
    {
        int s = two.x, d = two.y;
        float nrm = g_dinv[s] * g_dinv[d];
        int pos = rowstart(d) + atomicAdd(&g_fill[d], 1);
        g_csr[pos] = make_int2(s, __float_as_int(nrm));
    }
    if (e0 + 1 < E) {
        int s = two.z, d = two.w;
        float nrm = g_dinv[s] * g_dinv[d];
        int pos = rowstart(d) + atomicAdd(&g_fill[d], 1);
        g_csr[pos] = make_int2(s, __float_as_int(nrm));
    }
}

// ---- gather1 + gemm2 fused (fp16 h1 source) -------------------------------
// 16 nodes/block, 16 threads/node. Phase 1: t = relu(dinv^2*h1 + sum + b1)
// into smem. Phase 2: h2[node][f] = dot(t, W2[:,f]) per thread.
__global__ __launch_bounds__(256) void k_g1g2(const float* __restrict__ b1,
                                              const float* __restrict__ W2, int N) {
    __shared__ float ts[16][68];
    __shared__ float W2t[16][68];   // transposed W2: [f][k]
    __shared__ float b1s[64];
    int tid = threadIdx.x;
    for (int i = tid; i < 64 * 16; i += 256) W2t[i & 15][i >> 4] = W2[i];
    if (tid < 64) b1s[tid] = b1[tid];

    int li = tid >> 4, c = tid & 15;
    int node = blockIdx.x * 16 + li;
    bool valid = node < N;
    if (!valid) node = N - 1;   // clamp: redundant-but-valid, no sync divergence

    float di = g_dinv[node];
    float sc = di * di;
    float4 acc = h1load(node, c);
    acc.x *= sc; acc.y *= sc; acc.z *= sc; acc.w *= sc;
    int e = rowstart(node);
    int end = e + g_incnt[node];
    for (; e + 1 < end; e += 2) {
        int2 c0 = g_csr[e], c1 = g_csr[e + 1];
        float n0 = __int_as_float(c0.y), n1 = __int_as_float(c1.y);
        float4 v0 = h1load(c0.x, c);
        float4 v1 = h1load(c1.x, c);
        acc.x += v0.x * n0; acc.y += v0.y * n0;
        acc.z += v0.z * n0; acc.w += v0.w * n0;
        acc.x += v1.x * n1; acc.y += v1.y * n1;
        acc.z += v1.z * n1; acc.w += v1.w * n1;
    }
    if (e < end) {
        int2 c0 = g_csr[e];
        float n0 = __int_as_float(c0.y);
        float4 v0 = h1load(c0.x, c);
        acc.x += v0.x * n0; acc.y += v0.y * n0;
        acc.z += v0.z * n0; acc.w += v0.w * n0;
    }
    float4 b = *(const float4*)&b1s[c * 4];
    acc.x = fmaxf(acc.x + b.x, 0.f);
    acc.y = fmaxf(acc.y + b.y, 0.f);
    acc.z = fmaxf(acc.z + b.z, 0.f);
    acc.w = fmaxf(acc.w + b.w, 0.f);
    *(float4*)&ts[li][c * 4] = acc;
    __syncthreads();

    float h2 = 0.f;
    #pragma unroll
    for (int k = 0; k < 64; k += 4) {
        float4 t = *(const float4*)&ts[li][k];
        float4 w = *(const float4*)&W2t[c][k];
        h2 += t.x * w.x + t.y * w.y + t.z * w.z + t.w * w.w;
    }
    if (valid) g_h2[(size_t)node * OUT_CH + c] = h2;
}

// ---- gather2 + bias + log_softmax + counter-zero tail ---------------------
// 4 threads/node; softmax via 4-lane butterfly shuffles. Each node's lane 0
// zeroes its incnt/fill AFTER the last read -> arrays are zero for next call.
__global__ __launch_bounds__(256) void k_gather2(float* __restrict__ out,
                                                 const float* __restrict__ b2, int N) {
    int tid = threadIdx.x;
    int li = tid >> 2, c = tid & 3;
    int node = blockIdx.x * 64 + li;
    if (node >= N) return;
    float di = g_dinv[node];
    float sc = di * di;
    float4 acc = ((const float4*)(g_h2 + (size_t)node * OUT_CH))[c];
    acc.x *= sc; acc.y *= sc; acc.z *= sc; acc.w *= sc;
    int e = rowstart(node);
    int end = e + g_incnt[node];                 // all 4 lanes load together
    if (c == 0) { g_incnt[node] = 0; g_fill[node] = 0; }   // warp-ordered after load
    for (; e + 1 < end; e += 2) {
        int2 c0 = g_csr[e], c1 = g_csr[e + 1];
        float n0 = __int_as_float(c0.y), n1 = __int_as_float(c1.y);
        float4 v0 = ((const float4*)(g_h2 + (size_t)c0.x * OUT_CH))[c];
        float4 v1 = ((const float4*)(g_h2 + (size_t)c1.x * OUT_CH))[c];
        acc.x += v0.x * n0; acc.y += v0.y * n0;
        acc.z += v0.z * n0; acc.w += v0.w * n0;
        acc.x += v1.x * n1; acc.y += v1.y * n1;
        acc.z += v1.z * n1; acc.w += v1.w * n1;
    }
    if (e < end) {
        int2 c0 = g_csr[e];
        float n0 = __int_as_float(c0.y);
        float4 v0 = ((const float4*)(g_h2 + (size_t)c0.x * OUT_CH))[c];
        acc.x += v0.x * n0; acc.y += v0.y * n0;
        acc.z += v0.z * n0; acc.w += v0.w * n0;
    }
    float4 b = ((const float4*)b2)[c];
    acc.x += b.x; acc.y += b.y; acc.z += b.z; acc.w += b.w;
    float m = fmaxf(fmaxf(acc.x, acc.y), fmaxf(acc.z, acc.w));
    m = fmaxf(m, __shfl_xor_sync(0xffffffffu, m, 1));
    m = fmaxf(m, __shfl_xor_sync(0xffffffffu, m, 2));
    float se = expf(acc.x - m) + expf(acc.y - m) + expf(acc.z - m) + expf(acc.w - m);
    se += __shfl_xor_sync(0xffffffffu, se, 1);
    se += __shfl_xor_sync(0xffffffffu, se, 2);
    float l = m + logf(se);
    acc.x -= l; acc.y -= l; acc.z -= l; acc.w -= l;
    ((float4*)(out + (size_t)node * OUT_CH))[c] = acc;
}

// ---------------------------------------------------------------------------
extern "C" void kernel_launch(void* const* d_in, const int* in_sizes, int n_in,
                              void* d_out, int out_size) {
    const float* x  = (const float*)d_in[0];
    const void*  ei = d_in[1];
    const float* W1 = (const float*)d_in[2];
    const float* b1 = (const float*)d_in[3];
    const float* W2 = (const float*)d_in[4];
    const float* b2 = (const float*)d_in[5];
    float* out = (float*)d_out;

    int N = in_sizes[0] / IN_CH;
    long long E = in_sizes[1] / 2;

    int nwords = (int)((E < 512) ? E : 512);
    int nbG = (N + 127) / 128;
    int nchunks = (int)((E + PREP_CHUNK - 1) / PREP_CHUNK);
    int npool = nbG + nchunks;
    if (npool < 4 * nchunks) npool = 4 * nchunks;  // ensure all chunks covered
    int nbS = (N + 255) / 256;
    int nbF = (int)((E + 511) / 512);

    k_pool<<<npool, 256>>>(x, ei, W1, N, E, nbG, nchunks, nwords);
    k_scan<<<nbS, 256>>>(N, nbS);
    k_fill<<<nbF, 256>>>(E);
    k_g1g2<<<(N + 15) / 16, 256>>>(b1, W2, N);
    k_gather2<<<(N + 63) / 64, 256>>>(out, b2, N);
}

// round 8
// speedup vs baseline: 1.7715x; 1.1774x over previous
#include <cuda_runtime.h>
#include <cuda_fp16.h>

// ---------------------------------------------------------------------------
// GCN 2-layer, round 8: tf32 tensor-core GEMM1, fp16 h1, 8-thread/node
// gather1+gemm2, 5 launches.
// ---------------------------------------------------------------------------

#define MAXN 131072
#define MAXE 4194304
#define IN_CH 256
#define HID 64
#define OUT_CH 16
#define PREP_CHUNK 8192

__device__ __half2 g_h1h[(size_t)MAXN * 32];   // h1 fp16, 32 half2 (=128B) per row
__device__ float g_h2[(size_t)MAXN * OUT_CH];
__device__ float g_dinv[MAXN];
__device__ int   g_incnt[MAXN];      // zero at entry (static init / gather2 tail)
__device__ int   g_rowstart[MAXN];
__device__ int   g_fill[MAXN];       // zero at entry (same mechanism)
__device__ int   g_blocksum[1024];
__device__ int   g_scan_count;       // zero at entry; last scan block resets
__device__ int2  g_edge[MAXE];
__device__ int2  g_csr[MAXE];        // (src, norm-bits) grouped by dst

__device__ __forceinline__ int rowstart(int i) {
    return g_rowstart[i] + g_blocksum[i >> 8];
}

__device__ __forceinline__ unsigned f2tf32(float f) {
    unsigned u;
    asm("cvt.rna.tf32.f32 %0, %1;" : "=r"(u) : "f"(f));
    return u;
}

__device__ __forceinline__ void mma_tf32(float4& d, unsigned a0, unsigned a1,
                                         unsigned a2, unsigned a3,
                                         unsigned b0, unsigned b1) {
    asm volatile(
        "mma.sync.aligned.m16n8k8.row.col.f32.tf32.tf32.f32 "
        "{%0,%1,%2,%3},{%4,%5,%6,%7},{%8,%9},{%0,%1,%2,%3};"
        : "+f"(d.x), "+f"(d.y), "+f"(d.z), "+f"(d.w)
        : "r"(a0), "r"(a1), "r"(a2), "r"(a3), "r"(b0), "r"(b1));
}

// ---- pool: tf32 TC gemm1 tiles interleaved with edge-decode chunks --------
// Ticket q%4==3 (while chunks remain) -> prep chunk; else gemm tile.
#define KC 32   // k-chunk
__global__ __launch_bounds__(256) void k_pool(const float* __restrict__ x,
                                              const void* __restrict__ ei,
                                              const float* __restrict__ W1,
                                              int N, long long E,
                                              int nbG, int nchunks, int nwords) {
    __shared__ unsigned Xs[128][36];  // tf32 bits; bank(row,k)=(4*(row&7)+k)%32 distinct
    __shared__ unsigned Ws[KC][72];   // tf32 bits; bank(k,n)=(8k+n)%32 distinct
    int tid = threadIdx.x;
    int q = blockIdx.x;
    int lane = tid & 31, w = tid >> 5;

    bool isprep = ((q & 3) == 3) && ((q >> 2) < nchunks);
    if (isprep) {
        // local dtype probe (L2-cached, cheap)
        const long long* p = (const long long*)ei;
        int ok = 1;
        #pragma unroll
        for (int j = 0; j < 2; j++) {
            int wd = tid + j * 256;
            if (wd < nwords) {
                long long v = __ldg(p + wd);
                if (v < 0 || v >= (long long)N) ok = 0;
            }
        }
        int is64 = __syncthreads_and(ok);
        long long s0 = (long long)(q >> 2) * PREP_CHUNK;
        long long s1 = s0 + PREP_CHUNK; if (s1 > E) s1 = E;
        if (is64) {
            const long long* pp = (const long long*)ei;
            for (long long e = s0 + tid; e < s1; e += 256) {
                int s = (int)__ldg(pp + e);
                int d = (int)__ldg(pp + E + e);
                g_edge[e] = make_int2(s, d);
                atomicAdd(&g_incnt[d], 1);
            }
        } else {
            const int* pp = (const int*)ei;
            for (long long e = s0 + tid; e < s1; e += 256) {
                int s = __ldg(pp + e);
                int d = __ldg(pp + E + e);
                g_edge[e] = make_int2(s, d);
                atomicAdd(&g_incnt[d], 1);
            }
        }
        return;
    }

    int g = q - min(q >> 2, nchunks);
    if (g >= nbG) return;

    // ---- gemm1 tile: 128 nodes x 64 feats; warp w owns rows w*16..w*16+15
    int node0 = g * 128;
    int la3 = lane & 3, lg2 = lane >> 2;

    float4 acc[8];
    #pragma unroll
    for (int t = 0; t < 8; t++) acc[t] = make_float4(0.f, 0.f, 0.f, 0.f);

    for (int kk = 0; kk < IN_CH; kk += KC) {
        // stage X tile (tf32 bits): 128 rows x 32 k
        #pragma unroll
        for (int j = 0; j < 4; j++) {
            int idx = tid + j * 256;          // 1024 float4 slots
            int n = idx >> 3, kq = idx & 7;
            int gnode = node0 + n;
            float4 v = (gnode < N)
                ? *(const float4*)(x + (size_t)gnode * IN_CH + kk + kq * 4)
                : make_float4(0.f, 0.f, 0.f, 0.f);
            Xs[n][kq * 4 + 0] = f2tf32(v.x);
            Xs[n][kq * 4 + 1] = f2tf32(v.y);
            Xs[n][kq * 4 + 2] = f2tf32(v.z);
            Xs[n][kq * 4 + 3] = f2tf32(v.w);
        }
        // stage W tile (tf32 bits): 32 k x 64 n
        #pragma unroll
        for (int j = 0; j < 8; j++) {
            int idx = tid + j * 256;          // 2048 scalars
            int k = idx >> 6, n = idx & 63;
            Ws[k][n] = f2tf32(W1[(size_t)(kk + k) * 64 + n]);
        }
        __syncthreads();
        #pragma unroll
        for (int ks = 0; ks < KC; ks += 8) {
            int r0 = w * 16 + lg2;
            unsigned a0 = Xs[r0][ks + la3];
            unsigned a1 = Xs[r0 + 8][ks + la3];
            unsigned a2 = Xs[r0][ks + la3 + 4];
            unsigned a3 = Xs[r0 + 8][ks + la3 + 4];
            #pragma unroll
            for (int t = 0; t < 8; t++) {
                unsigned b0 = Ws[ks + la3][t * 8 + lg2];
                unsigned b1 = Ws[ks + la3 + 4][t * 8 + lg2];
                mma_tf32(acc[t], a0, a1, a2, a3, b0, b1);
            }
        }
        __syncthreads();
    }
    // epilogue: write h1 as fp16. c0,c1 -> row lo; c2,c3 -> row hi.
    int rlo = node0 + w * 16 + lg2;
    int rhi = rlo + 8;
    #pragma unroll
    for (int t = 0; t < 8; t++) {
        int h2idx = t * 4 + la3;   // half2 column index (cols 8t+2*la3, +1)
        if (rlo < N) g_h1h[(size_t)rlo * 32 + h2idx] = __floats2half2_rn(acc[t].x, acc[t].y);
        if (rhi < N) g_h1h[(size_t)rhi * 32 + h2idx] = __floats2half2_rn(acc[t].z, acc[t].w);
    }
}

// ---- single-pass scan: block scans + last block scans the block sums ------
__global__ __launch_bounds__(256) void k_scan(int N, int nbS) {
    __shared__ int wsum[8];
    __shared__ int sA[512], sB[512];
    __shared__ int s_last;
    int tid = threadIdx.x, lane = tid & 31, wid = tid >> 5;
    int cb = blockIdx.x;
    int i = cb * 256 + tid;
    int v = (i < N) ? g_incnt[i] : 0;
    if (i < N) g_dinv[i] = rsqrtf((float)(v + 1));  // +1 self-loop
    int xv = v;
    #pragma unroll
    for (int o = 1; o < 32; o <<= 1) {
        int y = __shfl_up_sync(0xffffffffu, xv, o);
        if (lane >= o) xv += y;
    }
    if (lane == 31) wsum[wid] = xv;
    __syncthreads();
    if (wid == 0) {
        int s = (lane < 8) ? wsum[lane] : 0;
        #pragma unroll
        for (int o = 1; o < 8; o <<= 1) {
            int y = __shfl_up_sync(0xffffffffu, s, o);
            if (lane >= o) s += y;
        }
        if (lane < 8) wsum[lane] = s;
    }
    __syncthreads();
    int excl = xv - v + (wid > 0 ? wsum[wid - 1] : 0);
    if (i < N) g_rowstart[i] = excl;
    if (tid == 255) {
        g_blocksum[cb] = excl + v;
        __threadfence();
        s_last = (atomicAdd(&g_scan_count, 1) == nbS - 1) ? 1 : 0;
    }
    __syncthreads();
    if (s_last) {
        __threadfence();
        int v0 = (tid < nbS) ? g_blocksum[tid] : 0;
        int v1 = (tid + 256 < nbS) ? g_blocksum[tid + 256] : 0;
        sA[tid] = v0; sA[tid + 256] = v1;
        __syncthreads();
        int* src = sA; int* dst = sB;
        for (int o = 1; o < 512; o <<= 1) {
            dst[tid]       = src[tid]       + ((tid >= o)       ? src[tid - o]       : 0);
            dst[tid + 256] = src[tid + 256] + ((tid + 256 >= o) ? src[tid + 256 - o] : 0);
            __syncthreads();
            int* t = src; src = dst; dst = t;
        }
        if (tid < nbS) g_blocksum[tid] = src[tid] - v0;
        if (tid + 256 < nbS) g_blocksum[tid + 256] = src[tid + 256] - v1;
        if (tid == 0) g_scan_count = 0;
    }
}

// ---- fill CSR: (src, norm) grouped by dst ---------------------------------
__global__ __launch_bounds__(256) void k_fill(long long E) {
    long long e0 = ((long long)blockIdx.x * 256 + threadIdx.x) * 2;
    if (e0 >= E) return;
    int4 two = *(const int4*)&g_edge[e0];
    {
        int s = two.x, d = two.y;
        float nrm = g_dinv[s] * g_dinv[d];
        int pos = rowstart(d) + atomicAdd(&g_fill[d], 1);
        g_csr[pos] = make_int2(s, __float_as_int(nrm));
    }
    if (e0 + 1 < E) {
        int s = two.z, d = two.w;
        float nrm = g_dinv[s] * g_dinv[d];
        int pos = rowstart(d) + atomicAdd(&g_fill[d], 1);
        g_csr[pos] = make_int2(s, __float_as_int(nrm));
    }
}

// accumulate 8 fp16 feats (uint4) scaled by n into acc[8]
__device__ __forceinline__ void acc8(float* acc, uint4 u, float n) {
    __half2* h = (__half2*)&u;
    #pragma unroll
    for (int i = 0; i < 4; i++) {
        float2 f = __half22float2(h[i]);
        acc[2 * i]     += f.x * n;
        acc[2 * i + 1] += f.y * n;
    }
}

// ---- gather1 + gemm2 fused: 32 nodes/block, 8 threads/node ----------------
__global__ __launch_bounds__(256) void k_g1g2(const float* __restrict__ b1,
                                              const float* __restrict__ W2, int N) {
    __shared__ float ts[32][68];
    __shared__ float W2t[16][68];   // transposed W2: [f][k]
    __shared__ float b1s[64];
    int tid = threadIdx.x;
    for (int i = tid; i < 64 * 16; i += 256) W2t[i & 15][i >> 4] = W2[i];
    if (tid < 64) b1s[tid] = b1[tid];

    int li = tid >> 3, c = tid & 7;   // node-in-block, 16B chunk
    int node = blockIdx.x * 32 + li;
    bool valid = node < N;
    if (!valid) node = N - 1;          // clamp: redundant-but-valid

    const uint4* selfrow = (const uint4*)(g_h1h + (size_t)node * 32);
    float di = g_dinv[node];
    float sc = di * di;
    float acc[8] = {0, 0, 0, 0, 0, 0, 0, 0};
    acc8(acc, selfrow[c], sc);

    int e = rowstart(node);
    int end = e + g_incnt[node];
    for (; e + 1 < end; e += 2) {
        int2 c0 = g_csr[e], c1 = g_csr[e + 1];
        uint4 v0 = ((const uint4*)(g_h1h + (size_t)c0.x * 32))[c];
        uint4 v1 = ((const uint4*)(g_h1h + (size_t)c1.x * 32))[c];
        acc8(acc, v0, __int_as_float(c0.y));
        acc8(acc, v1, __int_as_float(c1.y));
    }
    if (e < end) {
        int2 c0 = g_csr[e];
        uint4 v0 = ((const uint4*)(g_h1h + (size_t)c0.x * 32))[c];
        acc8(acc, v0, __int_as_float(c0.y));
    }
    #pragma unroll
    for (int i = 0; i < 8; i++)
        acc[i] = fmaxf(acc[i] + b1s[c * 8 + i], 0.f);
    *(float4*)&ts[li][c * 8]     = make_float4(acc[0], acc[1], acc[2], acc[3]);
    *(float4*)&ts[li][c * 8 + 4] = make_float4(acc[4], acc[5], acc[6], acc[7]);
    __syncthreads();

    // phase 2: 512 (node,f) outputs, 2 per thread
    int f = tid & 15;
    #pragma unroll
    for (int rep = 0; rep < 2; rep++) {
        int n2 = (tid >> 4) + rep * 16;
        float h2 = 0.f;
        #pragma unroll
        for (int k = 0; k < 64; k += 4) {
            float4 t = *(const float4*)&ts[n2][k];
            float4 wv = *(const float4*)&W2t[f][k];
            h2 += t.x * wv.x + t.y * wv.y + t.z * wv.z + t.w * wv.w;
        }
        int gnode = blockIdx.x * 32 + n2;
        if (gnode < N) g_h2[(size_t)gnode * OUT_CH + f] = h2;
    }
}

// ---- gather2 + bias + log_softmax + counter-zero tail ---------------------
__global__ __launch_bounds__(256) void k_gather2(float* __restrict__ out,
                                                 const float* __restrict__ b2, int N) {
    int tid = threadIdx.x;
    int li = tid >> 2, c = tid & 3;
    int node = blockIdx.x * 64 + li;
    if (node >= N) return;
    float di = g_dinv[node];
    float sc = di * di;
    float4 acc = ((const float4*)(g_h2 + (size_t)node * OUT_CH))[c];
    acc.x *= sc; acc.y *= sc; acc.z *= sc; acc.w *= sc;
    int e = rowstart(node);
    int end = e + g_incnt[node];
    if (c == 0) { g_incnt[node] = 0; g_fill[node] = 0; }  // zero for next call
    for (; e + 1 < end; e += 2) {
        int2 c0 = g_csr[e], c1 = g_csr[e + 1];
        float n0 = __int_as_float(c0.y), n1 = __int_as_float(c1.y);
        float4 v0 = ((const float4*)(g_h2 + (size_t)c0.x * OUT_CH))[c];
        float4 v1 = ((const float4*)(g_h2 + (size_t)c1.x * OUT_CH))[c];
        acc.x += v0.x * n0; acc.y += v0.y * n0;
        acc.z += v0.z * n0; acc.w += v0.w * n0;
        acc.x += v1.x * n1; acc.y += v1.y * n1;
        acc.z += v1.z * n1; acc.w += v1.w * n1;
    }
    if (e < end) {
        int2 c0 = g_csr[e];
        float n0 = __int_as_float(c0.y);
        float4 v0 = ((const float4*)(g_h2 + (size_t)c0.x * OUT_CH))[c];
        acc.x += v0.x * n0; acc.y += v0.y * n0;
        acc.z += v0.z * n0; acc.w += v0.w * n0;
    }
    float4 b = ((const float4*)b2)[c];
    acc.x += b.x; acc.y += b.y; acc.z += b.z; acc.w += b.w;
    float m = fmaxf(fmaxf(acc.x, acc.y), fmaxf(acc.z, acc.w));
    m = fmaxf(m, __shfl_xor_sync(0xffffffffu, m, 1));
    m = fmaxf(m, __shfl_xor_sync(0xffffffffu, m, 2));
    float se = expf(acc.x - m) + expf(acc.y - m) + expf(acc.z - m) + expf(acc.w - m);
    se += __shfl_xor_sync(0xffffffffu, se, 1);
    se += __shfl_xor_sync(0xffffffffu, se, 2);
    float l = m + logf(se);
    acc.x -= l; acc.y -= l; acc.z -= l; acc.w -= l;
    ((float4*)(out + (size_t)node * OUT_CH))[c] = acc;
}

// ---------------------------------------------------------------------------
extern "C" void kernel_launch(void* const* d_in, const int* in_sizes, int n_in,
                              void* d_out, int out_size) {
    const float* x  = (const float*)d_in[0];
    const void*  ei = d_in[1];
    const float* W1 = (const float*)d_in[2];
    const float* b1 = (const float*)d_in[3];
    const float* W2 = (const float*)d_in[4];
    const float* b2 = (const float*)d_in[5];
    float* out = (float*)d_out;

    int N = in_sizes[0] / IN_CH;
    long long E = in_sizes[1] / 2;

    int nwords = (int)((E < 512) ? E : 512);
    int nbG = (N + 127) / 128;
    int nchunks = (int)((E + PREP_CHUNK - 1) / PREP_CHUNK);
    int npool = nbG + nchunks;
    if (npool < 4 * nchunks) npool = 4 * nchunks;  // ticket map covers all chunks
    int nbS = (N + 255) / 256;
    int nbF = (int)((E + 511) / 512);

    k_pool<<<npool, 256>>>(x, ei, W1, N, E, nbG, nchunks, nwords);
    k_scan<<<nbS, 256>>>(N, nbS);
    k_fill<<<nbF, 256>>>(E);
    k_g1g2<<<(N + 31) / 32, 256>>>(b1, W2, N);
    k_gather2<<<(N + 63) / 64, 256>>>(out, b2, N);
}